// round 2
// baseline (speedup 1.0000x reference)
#include <cuda_runtime.h>
#include <cstdint>

// Problem constants (fixed by the dataset)
#define B_SZ   2
#define S_LEN  2048
#define NH     16
#define DH     64
#define DM     1024
#define M_ROWS (B_SZ * S_LEN)   // 4096

// Scratch: head-split projections [B,H,S,Dh] and attention context [B,S,DM]
__device__ float g_q[B_SZ * NH * S_LEN * DH];
__device__ float g_k[B_SZ * NH * S_LEN * DH];
__device__ float g_v[B_SZ * NH * S_LEN * DH];
__device__ float g_ctx[(size_t)M_ROWS * DM];

// ---------------------------------------------------------------------------
// Double-buffered NT GEMM core: C = A @ W^T + bias.
// A [M,K] row-major, W [N,K] row-major. 128x128 CTA tile, BK=16, 256 threads,
// 8x8 per thread (split 4+4 sub-tiles for conflict-free float4 SMEM reads).
// Global loads for step k+1 are issued before the FMA loop of step k
// (register prefetch), stored to the alternate SMEM buffer after; one
// __syncthreads per K-step.
// headsplit=1: scatter C[m,n] into [B,H,S,Dh]. headsplit=0: row-major [M,N].
// ---------------------------------------------------------------------------
__device__ __forceinline__ void gemm_nt_body(
    const float* __restrict__ A, const float* __restrict__ W,
    const float* __restrict__ bias, float* __restrict__ C,
    int K, int N, int headsplit, int m0, int n0)
{
    __shared__ float As[2][16][128];
    __shared__ float Bs[2][16][128];

    const int tid = threadIdx.x;
    const int tx = tid & 15;
    const int ty = tid >> 4;

    // Per-thread staging coords: 2 float4s from A, 2 from W per K-step
    const int row0 = tid >> 2;             // 0..63
    const int row1 = row0 + 64;            // 64..127
    const int c4   = (tid & 3) << 2;       // 0,4,8,12

    const float* Ap0 = A + (size_t)(m0 + row0) * K + c4;
    const float* Ap1 = A + (size_t)(m0 + row1) * K + c4;
    const float* Wp0 = W + (size_t)(n0 + row0) * K + c4;
    const float* Wp1 = W + (size_t)(n0 + row1) * K + c4;

    float acc[8][8];
#pragma unroll
    for (int i = 0; i < 8; i++)
#pragma unroll
        for (int j = 0; j < 8; j++) acc[i][j] = 0.0f;

    // Prologue: stage tile 0
    {
        float4 a0 = *(const float4*)(Ap0);
        float4 a1 = *(const float4*)(Ap1);
        float4 b0 = *(const float4*)(Wp0);
        float4 b1 = *(const float4*)(Wp1);
        As[0][c4 + 0][row0] = a0.x; As[0][c4 + 1][row0] = a0.y;
        As[0][c4 + 2][row0] = a0.z; As[0][c4 + 3][row0] = a0.w;
        As[0][c4 + 0][row1] = a1.x; As[0][c4 + 1][row1] = a1.y;
        As[0][c4 + 2][row1] = a1.z; As[0][c4 + 3][row1] = a1.w;
        Bs[0][c4 + 0][row0] = b0.x; Bs[0][c4 + 1][row0] = b0.y;
        Bs[0][c4 + 2][row0] = b0.z; Bs[0][c4 + 3][row0] = b0.w;
        Bs[0][c4 + 0][row1] = b1.x; Bs[0][c4 + 1][row1] = b1.y;
        Bs[0][c4 + 2][row1] = b1.z; Bs[0][c4 + 3][row1] = b1.w;
    }
    __syncthreads();

    int buf = 0;
    const int nsteps = K >> 4;
    for (int step = 0; step < nsteps; step++) {
        const bool has_next = (step + 1) < nsteps;
        float4 a0, a1, b0, b1;
        if (has_next) {
            int koff = (step + 1) << 4;
            a0 = *(const float4*)(Ap0 + koff);
            a1 = *(const float4*)(Ap1 + koff);
            b0 = *(const float4*)(Wp0 + koff);
            b1 = *(const float4*)(Wp1 + koff);
        }

#pragma unroll
        for (int kk = 0; kk < 16; kk++) {
            float ar[8], br[8];
            *(float4*)&ar[0] = *(const float4*)&As[buf][kk][ty * 4];
            *(float4*)&ar[4] = *(const float4*)&As[buf][kk][64 + ty * 4];
            *(float4*)&br[0] = *(const float4*)&Bs[buf][kk][tx * 4];
            *(float4*)&br[4] = *(const float4*)&Bs[buf][kk][64 + tx * 4];
#pragma unroll
            for (int i = 0; i < 8; i++)
#pragma unroll
                for (int j = 0; j < 8; j++)
                    acc[i][j] = fmaf(ar[i], br[j], acc[i][j]);
        }

        if (has_next) {
            int nb = buf ^ 1;
            As[nb][c4 + 0][row0] = a0.x; As[nb][c4 + 1][row0] = a0.y;
            As[nb][c4 + 2][row0] = a0.z; As[nb][c4 + 3][row0] = a0.w;
            As[nb][c4 + 0][row1] = a1.x; As[nb][c4 + 1][row1] = a1.y;
            As[nb][c4 + 2][row1] = a1.z; As[nb][c4 + 3][row1] = a1.w;
            Bs[nb][c4 + 0][row0] = b0.x; Bs[nb][c4 + 1][row0] = b0.y;
            Bs[nb][c4 + 2][row0] = b0.z; Bs[nb][c4 + 3][row0] = b0.w;
            Bs[nb][c4 + 0][row1] = b1.x; Bs[nb][c4 + 1][row1] = b1.y;
            Bs[nb][c4 + 2][row1] = b1.z; Bs[nb][c4 + 3][row1] = b1.w;
            __syncthreads();
            buf = nb;
        }
    }

#pragma unroll
    for (int i = 0; i < 8; i++) {
        int mrow = m0 + ((i < 4) ? (ty * 4 + i) : (64 + ty * 4 + i - 4));
#pragma unroll
        for (int j = 0; j < 8; j++) {
            int ncol = n0 + ((j < 4) ? (tx * 4 + j) : (64 + tx * 4 + j - 4));
            float v = acc[i][j] + bias[ncol];
            if (headsplit) {
                int b = mrow >> 11;           // S_LEN = 2048
                int s = mrow & (S_LEN - 1);
                int h = ncol >> 6;            // DH = 64
                int d = ncol & (DH - 1);
                C[(((size_t)b * NH + h) * S_LEN + s) * DH + d] = v;
            } else {
                C[(size_t)mrow * N + ncol] = v;
            }
        }
    }
}

// Fused Q/K/V projection: blockIdx.z selects which projection this CTA does.
// One launch -> 768 CTAs -> tails of the three GEMMs overlap.
__global__ __launch_bounds__(256) void qkv_gemm_kernel(
    const float* __restrict__ Q, const float* __restrict__ K,
    const float* __restrict__ V,
    const float* __restrict__ Wq, const float* __restrict__ bq,
    const float* __restrict__ Wk, const float* __restrict__ bk,
    const float* __restrict__ Wv, const float* __restrict__ bv,
    float* __restrict__ gq, float* __restrict__ gk, float* __restrict__ gv)
{
    const float *A, *W, *bias;
    float* C;
    if (blockIdx.z == 0)      { A = Q; W = Wq; bias = bq; C = gq; }
    else if (blockIdx.z == 1) { A = K; W = Wk; bias = bk; C = gk; }
    else                      { A = V; W = Wv; bias = bv; C = gv; }
    gemm_nt_body(A, W, bias, C, DM, DM, 1, blockIdx.y * 128, blockIdx.x * 128);
}

// Output projection: plain row-major GEMM.
__global__ __launch_bounds__(256) void out_gemm_kernel(
    const float* __restrict__ A, const float* __restrict__ W,
    const float* __restrict__ bias, float* __restrict__ C)
{
    gemm_nt_body(A, W, bias, C, DM, DM, 0, blockIdx.y * 128, blockIdx.x * 128);
}

// ---------------------------------------------------------------------------
// Flash attention (causal + key padding), fp32, per (b, h, q-tile of 64).
// 256 threads as 16x16; each thread owns a 4x4 score tile and 4x4 of O.
// K is staged transposed (d-major) into SMEM with an XOR swizzle
// (col -> (col+d)&63) to keep transpose STS and score LDS at <=2-way
// conflicts; P overlays the Kt buffer so static SMEM is exactly 48 KB.
// ---------------------------------------------------------------------------
__global__ __launch_bounds__(256) void attn_kernel(
    const float* __restrict__ Qh, const float* __restrict__ Kh,
    const float* __restrict__ Vh, const unsigned char* __restrict__ pad,
    float* __restrict__ ctx)
{
    __shared__ float Qs[64 * 64];   // [row][d], row-major
    __shared__ float KP[64 * 64];   // phase 1: Kt[d][col] swizzled; phase 2: P[row][col]
    __shared__ float Vs[64 * 64];   // [kpos][d], row-major

    const int tid = threadIdx.x;
    const int tx = tid & 15;
    const int ty = tid >> 4;
    const int qt = blockIdx.x;
    const int h  = blockIdx.y;
    const int b  = blockIdx.z;

    const size_t headoff = ((size_t)(b * NH + h)) * S_LEN * DH;
    const float* Qb = Qh + headoff;
    const float* Kb = Kh + headoff;
    const float* Vb = Vh + headoff;

    // Load + pre-scale Q tile (1/sqrt(64) = 0.125)
#pragma unroll
    for (int i = 0; i < 4; i++) {
        int idx = tid + i * 256;       // 1024 float4s
        int row = idx >> 4;            // 0..63
        int c   = (idx & 15) << 2;     // 0..60
        float4 v = *(const float4*)(Qb + (size_t)(qt * 64 + row) * DH + c);
        Qs[row * 64 + c + 0] = v.x * 0.125f;
        Qs[row * 64 + c + 1] = v.y * 0.125f;
        Qs[row * 64 + c + 2] = v.z * 0.125f;
        Qs[row * 64 + c + 3] = v.w * 0.125f;
    }

    float m_i[4], l_i[4], o[4][4];
#pragma unroll
    for (int i = 0; i < 4; i++) {
        m_i[i] = -1e30f;
        l_i[i] = 0.0f;
#pragma unroll
        for (int j = 0; j < 4; j++) o[i][j] = 0.0f;
    }

    for (int kt = 0; kt <= qt; kt++) {
        __syncthreads();   // protect prior-iteration KP/Vs readers (and Qs load at kt=0)

        // Stage K (transposed+swizzled) and V (row-major)
#pragma unroll
        for (int i = 0; i < 4; i++) {
            int idx = tid + i * 256;
            int row = idx >> 4;            // k position within tile
            int c   = (idx & 15) << 2;     // d base
            float4 kv = *(const float4*)(Kb + (size_t)(kt * 64 + row) * DH + c);
            KP[(c + 0) * 64 + ((row + c + 0) & 63)] = kv.x;
            KP[(c + 1) * 64 + ((row + c + 1) & 63)] = kv.y;
            KP[(c + 2) * 64 + ((row + c + 2) & 63)] = kv.z;
            KP[(c + 3) * 64 + ((row + c + 3) & 63)] = kv.w;
            float4 vv = *(const float4*)(Vb + (size_t)(kt * 64 + row) * DH + c);
            *(float4*)(Vs + row * 64 + c) = vv;
        }
        __syncthreads();

        // Scores: sc[i][j] = sum_d Qs[qrow][d] * Kt[d][kcol]
        float sc[4][4];
#pragma unroll
        for (int i = 0; i < 4; i++)
#pragma unroll
            for (int j = 0; j < 4; j++) sc[i][j] = 0.0f;

        for (int d = 0; d < 64; d++) {
            float br0 = KP[d * 64 + ((tx * 4 + 0 + d) & 63)];
            float br1 = KP[d * 64 + ((tx * 4 + 1 + d) & 63)];
            float br2 = KP[d * 64 + ((tx * 4 + 2 + d) & 63)];
            float br3 = KP[d * 64 + ((tx * 4 + 3 + d) & 63)];
#pragma unroll
            for (int i = 0; i < 4; i++) {
                float a = Qs[(ty * 4 + i) * 64 + d];
                sc[i][0] = fmaf(a, br0, sc[i][0]);
                sc[i][1] = fmaf(a, br1, sc[i][1]);
                sc[i][2] = fmaf(a, br2, sc[i][2]);
                sc[i][3] = fmaf(a, br3, sc[i][3]);
            }
        }

        // Mask: causal (diagonal tile only) + key padding
        const bool diag = (kt == qt);
#pragma unroll
        for (int j = 0; j < 4; j++) {
            int kj = kt * 64 + tx * 4 + j;
            bool pm = (pad[b * S_LEN + kj] != 0);
#pragma unroll
            for (int i = 0; i < 4; i++) {
                if (pm || (diag && (tx * 4 + j) > (ty * 4 + i)))
                    sc[i][j] = -1e9f;
            }
        }

        // Online softmax (rows live across a 16-lane tx-group; xor-shuffle reduce)
#pragma unroll
        for (int i = 0; i < 4; i++) {
            float rm = fmaxf(fmaxf(sc[i][0], sc[i][1]), fmaxf(sc[i][2], sc[i][3]));
#pragma unroll
            for (int off = 8; off >= 1; off >>= 1)
                rm = fmaxf(rm, __shfl_xor_sync(0xffffffffu, rm, off));
            float mnew = fmaxf(m_i[i], rm);
            float corr = __expf(m_i[i] - mnew);
            m_i[i] = mnew;
            float rs = 0.0f;
#pragma unroll
            for (int j = 0; j < 4; j++) {
                sc[i][j] = __expf(sc[i][j] - mnew);
                rs += sc[i][j];
            }
#pragma unroll
            for (int off = 8; off >= 1; off >>= 1)
                rs += __shfl_xor_sync(0xffffffffu, rs, off);
            l_i[i] = l_i[i] * corr + rs;
#pragma unroll
            for (int j = 0; j < 4; j++) o[i][j] *= corr;
        }

        __syncthreads();   // everyone done reading Kt before overlaying P
#pragma unroll
        for (int i = 0; i < 4; i++)
#pragma unroll
            for (int j = 0; j < 4; j++)
                KP[(ty * 4 + i) * 64 + tx * 4 + j] = sc[i][j];
        __syncthreads();

        // O += P @ V   (thread covers qrows ty*4.., dcols tx*4..)
        for (int j = 0; j < 64; j++) {
            float4 vv = *(const float4*)(Vs + j * 64 + tx * 4);
#pragma unroll
            for (int i = 0; i < 4; i++) {
                float p = KP[(ty * 4 + i) * 64 + j];
                o[i][0] = fmaf(p, vv.x, o[i][0]);
                o[i][1] = fmaf(p, vv.y, o[i][1]);
                o[i][2] = fmaf(p, vv.z, o[i][2]);
                o[i][3] = fmaf(p, vv.w, o[i][3]);
            }
        }
    }

    // Finalize and write context in [B,S,H*Dh] layout (= [4096,1024] row-major)
#pragma unroll
    for (int i = 0; i < 4; i++) {
        float inv = 1.0f / l_i[i];
        int s = qt * 64 + ty * 4 + i;
        float* dst = ctx + ((size_t)b * S_LEN + s) * DM + h * DH + tx * 4;
        dst[0] = o[i][0] * inv;
        dst[1] = o[i][1] * inv;
        dst[2] = o[i][2] * inv;
        dst[3] = o[i][3] * inv;
    }
}

// ---------------------------------------------------------------------------
// Launch. Inputs (metadata order): Q, K, V, attn_mask, padding_mask,
// Wq, bq, Wk, bk, Wv, bv, Wo, bo. attn_mask is exactly causal (k>q), computed
// analytically; padding_mask honored from the input.
// ---------------------------------------------------------------------------
extern "C" void kernel_launch(void* const* d_in, const int* in_sizes, int n_in,
                              void* d_out, int out_size)
{
    const float* Q  = (const float*)d_in[0];
    const float* K  = (const float*)d_in[1];
    const float* V  = (const float*)d_in[2];
    const unsigned char* pad = (const unsigned char*)d_in[4];
    const float* Wq = (const float*)d_in[5];
    const float* bq = (const float*)d_in[6];
    const float* Wk = (const float*)d_in[7];
    const float* bk = (const float*)d_in[8];
    const float* Wv = (const float*)d_in[9];
    const float* bv = (const float*)d_in[10];
    const float* Wo = (const float*)d_in[11];
    const float* bo = (const float*)d_in[12];
    float* out = (float*)d_out;

    float *gq, *gk, *gv, *gctx;
    cudaGetSymbolAddress((void**)&gq,   g_q);
    cudaGetSymbolAddress((void**)&gk,   g_k);
    cudaGetSymbolAddress((void**)&gv,   g_v);
    cudaGetSymbolAddress((void**)&gctx, g_ctx);

    dim3 gqkv(DM / 128, M_ROWS / 128, 3);  // (8, 32, 3) -> 768 CTAs, one launch
    qkv_gemm_kernel<<<gqkv, 256>>>(Q, K, V, Wq, bq, Wk, bk, Wv, bv, gq, gk, gv);

    dim3 ga(S_LEN / 64, NH, B_SZ);         // (32, 16, 2)
    attn_kernel<<<ga, 256>>>(gq, gk, gv, pad, gctx);

    dim3 gg(DM / 128, M_ROWS / 128);       // (8, 32)
    out_gemm_kernel<<<gg, 256>>>(gctx, Wo, bo, out);
}

// round 6
// speedup vs baseline: 1.2894x; 1.2894x over previous
#include <cuda_runtime.h>
#include <cuda_bf16.h>
#include <cstdint>

// Problem constants (fixed by the dataset)
#define B_SZ   2
#define S_LEN  2048
#define NH     16
#define DH     64
#define DM     1024
#define M_ROWS (B_SZ * S_LEN)   // 4096

// ---------------------------------------------------------------------------
// Scratch (device globals; no allocation allowed)
// ---------------------------------------------------------------------------
__device__ float g_q[B_SZ * NH * S_LEN * DH];
__device__ float g_k[B_SZ * NH * S_LEN * DH];
__device__ float g_v[B_SZ * NH * S_LEN * DH];
__device__ float g_ctx[(size_t)M_ROWS * DM];

// bf16 hi/lo splits of activations / weights / context
__device__ __nv_bfloat16 g_Qh[(size_t)M_ROWS * DM], g_Ql[(size_t)M_ROWS * DM];
__device__ __nv_bfloat16 g_Kh[(size_t)M_ROWS * DM], g_Kl[(size_t)M_ROWS * DM];
__device__ __nv_bfloat16 g_Vh[(size_t)M_ROWS * DM], g_Vl[(size_t)M_ROWS * DM];
__device__ __nv_bfloat16 g_Ch[(size_t)M_ROWS * DM], g_Cl[(size_t)M_ROWS * DM];
__device__ __nv_bfloat16 g_Wqh[DM * DM], g_Wql[DM * DM];
__device__ __nv_bfloat16 g_Wkh[DM * DM], g_Wkl[DM * DM];
__device__ __nv_bfloat16 g_Wvh[DM * DM], g_Wvl[DM * DM];
__device__ __nv_bfloat16 g_Woh[DM * DM], g_Wol[DM * DM];

// ---------------------------------------------------------------------------
// fp32 -> bf16 hi/lo split conversion
// ---------------------------------------------------------------------------
__global__ __launch_bounds__(256) void split_bf16_kernel(
    const float* __restrict__ x, __nv_bfloat16* __restrict__ hi,
    __nv_bfloat16* __restrict__ lo, int n4)  // n4 = n/4
{
    int i = blockIdx.x * 256 + threadIdx.x;
    if (i >= n4) return;
    float4 v = *(const float4*)(x + (size_t)i * 4);
    __nv_bfloat16 h0 = __float2bfloat16(v.x);
    __nv_bfloat16 h1 = __float2bfloat16(v.y);
    __nv_bfloat16 h2 = __float2bfloat16(v.z);
    __nv_bfloat16 h3 = __float2bfloat16(v.w);
    __nv_bfloat16 l0 = __float2bfloat16(v.x - __bfloat162float(h0));
    __nv_bfloat16 l1 = __float2bfloat16(v.y - __bfloat162float(h1));
    __nv_bfloat16 l2 = __float2bfloat16(v.z - __bfloat162float(h2));
    __nv_bfloat16 l3 = __float2bfloat16(v.w - __bfloat162float(h3));
    __nv_bfloat162 hp0(h0, h1), hp1(h2, h3), lp0(l0, l1), lp1(l2, l3);
    *(__nv_bfloat162*)(hi + (size_t)i * 4)     = hp0;
    *(__nv_bfloat162*)(hi + (size_t)i * 4 + 2) = hp1;
    *(__nv_bfloat162*)(lo + (size_t)i * 4)     = lp0;
    *(__nv_bfloat162*)(lo + (size_t)i * 4 + 2) = lp1;
}

// ---------------------------------------------------------------------------
// Warp-level bf16 MMA (m16n8k16, fp32 accumulate) — works on compute_103
// (no 'a'-feature instructions anywhere in this file).
// ---------------------------------------------------------------------------
__device__ __forceinline__ void mma_bf16(
    float& d0, float& d1, float& d2, float& d3,
    uint32_t a0, uint32_t a1, uint32_t a2, uint32_t a3,
    uint32_t b0, uint32_t b1)
{
    asm volatile(
        "mma.sync.aligned.m16n8k16.row.col.f32.bf16.bf16.f32 "
        "{%0,%1,%2,%3}, {%4,%5,%6,%7}, {%8,%9}, {%0,%1,%2,%3};"
        : "+f"(d0), "+f"(d1), "+f"(d2), "+f"(d3)
        : "r"(a0), "r"(a1), "r"(a2), "r"(a3), "r"(b0), "r"(b1));
}

// ---------------------------------------------------------------------------
// Tensor-core GEMM: C[M,N] = (Ah+Al) @ (Wh+Wl)^T + bias (3-term bf16 split).
// A [M,K], W [N,K], both K-major row-major bf16 pairs. CTA tile 128x128,
// BK=32, 256 threads (8 warps in 2x4, warp tile 64x32). Smem rows padded to
// 40 bf16 (80B) for conflict-free fragment LDS. Register prefetch of the
// next K-chunk overlaps global latency with tensor math.
// ---------------------------------------------------------------------------
#define BK   32
#define LDT  40   // smem row pitch in bf16 (32 data + 8 pad -> 80B, 16B-mult)

__device__ __forceinline__ void tc_gemm_body(
    const __nv_bfloat16* __restrict__ Ah, const __nv_bfloat16* __restrict__ Al,
    const __nv_bfloat16* __restrict__ Wh, const __nv_bfloat16* __restrict__ Wl,
    const float* __restrict__ bias, float* __restrict__ C,
    int headsplit, int m0, int n0)
{
    __shared__ __nv_bfloat16 sAh[128 * LDT];
    __shared__ __nv_bfloat16 sAl[128 * LDT];
    __shared__ __nv_bfloat16 sWh[128 * LDT];
    __shared__ __nv_bfloat16 sWl[128 * LDT];

    const int tid  = threadIdx.x;
    const int wid  = tid >> 5;
    const int lane = tid & 31;
    const int gid  = lane >> 2;     // 0..7
    const int tig  = lane & 3;      // 0..3
    const int wm   = (wid >> 2) * 64;   // warp m-offset within CTA tile
    const int wn   = (wid & 3) * 32;    // warp n-offset

    // Staging coords: per matrix, 2x float4 (8 bf16) per thread per step
    const int srow = tid >> 2;           // 0..63 (and +64)
    const int sc8  = (tid & 3) * 8;      // k-col base 0,8,16,24

    const __nv_bfloat16* pAh0 = Ah + (size_t)(m0 + srow) * DM + sc8;
    const __nv_bfloat16* pAh1 = Ah + (size_t)(m0 + srow + 64) * DM + sc8;
    const __nv_bfloat16* pAl0 = Al + (size_t)(m0 + srow) * DM + sc8;
    const __nv_bfloat16* pAl1 = Al + (size_t)(m0 + srow + 64) * DM + sc8;
    const __nv_bfloat16* pWh0 = Wh + (size_t)(n0 + srow) * DM + sc8;
    const __nv_bfloat16* pWh1 = Wh + (size_t)(n0 + srow + 64) * DM + sc8;
    const __nv_bfloat16* pWl0 = Wl + (size_t)(n0 + srow) * DM + sc8;
    const __nv_bfloat16* pWl1 = Wl + (size_t)(n0 + srow + 64) * DM + sc8;

    float acc[4][4][4];   // [mt][nt][d0..d3]
#pragma unroll
    for (int i = 0; i < 4; i++)
#pragma unroll
        for (int j = 0; j < 4; j++)
#pragma unroll
            for (int d = 0; d < 4; d++) acc[i][j][d] = 0.0f;

    float4 rA0, rA1, rL0, rL1, rW0, rW1, rV0, rV1;

    // Prologue: load chunk 0 and stage it
    rA0 = *(const float4*)pAh0;  rA1 = *(const float4*)pAh1;
    rL0 = *(const float4*)pAl0;  rL1 = *(const float4*)pAl1;
    rW0 = *(const float4*)pWh0;  rW1 = *(const float4*)pWh1;
    rV0 = *(const float4*)pWl0;  rV1 = *(const float4*)pWl1;
    *(float4*)&sAh[srow * LDT + sc8]        = rA0;
    *(float4*)&sAh[(srow + 64) * LDT + sc8] = rA1;
    *(float4*)&sAl[srow * LDT + sc8]        = rL0;
    *(float4*)&sAl[(srow + 64) * LDT + sc8] = rL1;
    *(float4*)&sWh[srow * LDT + sc8]        = rW0;
    *(float4*)&sWh[(srow + 64) * LDT + sc8] = rW1;
    *(float4*)&sWl[srow * LDT + sc8]        = rV0;
    *(float4*)&sWl[(srow + 64) * LDT + sc8] = rV1;
    __syncthreads();

    const int nsteps = DM / BK;   // 32
    for (int ch = 0; ch < nsteps; ch++) {
        const bool has_next = (ch + 1) < nsteps;
        if (has_next) {
            int ko = (ch + 1) * BK;
            rA0 = *(const float4*)(pAh0 + ko);  rA1 = *(const float4*)(pAh1 + ko);
            rL0 = *(const float4*)(pAl0 + ko);  rL1 = *(const float4*)(pAl1 + ko);
            rW0 = *(const float4*)(pWh0 + ko);  rW1 = *(const float4*)(pWh1 + ko);
            rV0 = *(const float4*)(pWl0 + ko);  rV1 = *(const float4*)(pWl1 + ko);
        }

#pragma unroll
        for (int ks = 0; ks < 2; ks++) {
            const int kin = ks * 16 + tig * 2;   // bf16 col of this thread's frags

            // A fragments (hi & lo) for 4 m-subtiles
            uint32_t ah[4][4], al[4][4];
#pragma unroll
            for (int mt = 0; mt < 4; mt++) {
                int r = (wm + mt * 16 + gid) * LDT + kin;
                ah[mt][0] = *(const uint32_t*)&sAh[r];
                ah[mt][1] = *(const uint32_t*)&sAh[r + 8 * LDT];
                ah[mt][2] = *(const uint32_t*)&sAh[r + 8];
                ah[mt][3] = *(const uint32_t*)&sAh[r + 8 * LDT + 8];
                al[mt][0] = *(const uint32_t*)&sAl[r];
                al[mt][1] = *(const uint32_t*)&sAl[r + 8 * LDT];
                al[mt][2] = *(const uint32_t*)&sAl[r + 8];
                al[mt][3] = *(const uint32_t*)&sAl[r + 8 * LDT + 8];
            }
            // B fragments (hi & lo) for 4 n-subtiles
            uint32_t bh[4][2], bl[4][2];
#pragma unroll
            for (int nt = 0; nt < 4; nt++) {
                int r = (wn + nt * 8 + gid) * LDT + kin;
                bh[nt][0] = *(const uint32_t*)&sWh[r];
                bh[nt][1] = *(const uint32_t*)&sWh[r + 8];
                bl[nt][0] = *(const uint32_t*)&sWl[r];
                bl[nt][1] = *(const uint32_t*)&sWl[r + 8];
            }

#pragma unroll
            for (int mt = 0; mt < 4; mt++)
#pragma unroll
                for (int nt = 0; nt < 4; nt++) {
                    float* d = acc[mt][nt];
                    mma_bf16(d[0], d[1], d[2], d[3],
                             ah[mt][0], ah[mt][1], ah[mt][2], ah[mt][3],
                             bh[nt][0], bh[nt][1]);
                    mma_bf16(d[0], d[1], d[2], d[3],
                             ah[mt][0], ah[mt][1], ah[mt][2], ah[mt][3],
                             bl[nt][0], bl[nt][1]);
                    mma_bf16(d[0], d[1], d[2], d[3],
                             al[mt][0], al[mt][1], al[mt][2], al[mt][3],
                             bh[nt][0], bh[nt][1]);
                }
        }

        if (has_next) {
            __syncthreads();   // everyone done reading before overwrite
            *(float4*)&sAh[srow * LDT + sc8]        = rA0;
            *(float4*)&sAh[(srow + 64) * LDT + sc8] = rA1;
            *(float4*)&sAl[srow * LDT + sc8]        = rL0;
            *(float4*)&sAl[(srow + 64) * LDT + sc8] = rL1;
            *(float4*)&sWh[srow * LDT + sc8]        = rW0;
            *(float4*)&sWh[(srow + 64) * LDT + sc8] = rW1;
            *(float4*)&sWl[srow * LDT + sc8]        = rV0;
            *(float4*)&sWl[(srow + 64) * LDT + sc8] = rV1;
            __syncthreads();
        }
    }

    // Epilogue: d0,d1 at (gid, tig*2..+1); d2,d3 at (gid+8, same cols)
#pragma unroll
    for (int mt = 0; mt < 4; mt++) {
#pragma unroll
        for (int nt = 0; nt < 4; nt++) {
            int c0 = n0 + wn + nt * 8 + tig * 2;
            float bx = bias[c0], by = bias[c0 + 1];
#pragma unroll
            for (int half = 0; half < 2; half++) {
                int mrow = m0 + wm + mt * 16 + gid + half * 8;
                float2 v;
                v.x = acc[mt][nt][half * 2 + 0] + bx;
                v.y = acc[mt][nt][half * 2 + 1] + by;
                if (headsplit) {
                    int b = mrow >> 11;           // S_LEN = 2048
                    int s = mrow & (S_LEN - 1);
                    int h = c0 >> 6;              // DH = 64
                    int d = c0 & (DH - 1);
                    *(float2*)&C[(((size_t)b * NH + h) * S_LEN + s) * DH + d] = v;
                } else {
                    *(float2*)&C[(size_t)mrow * DM + c0] = v;
                }
            }
        }
    }
}

// Fused Q/K/V projection: blockIdx.z selects the projection.
__global__ __launch_bounds__(256) void qkv_mma_kernel(
    const float* __restrict__ bq, const float* __restrict__ bk,
    const float* __restrict__ bv,
    float* __restrict__ gq, float* __restrict__ gk, float* __restrict__ gv)
{
    const __nv_bfloat16 *Ah, *Al, *Wh, *Wl;
    const float* bias; float* C;
    if (blockIdx.z == 0)      { Ah = g_Qh; Al = g_Ql; Wh = g_Wqh; Wl = g_Wql; bias = bq; C = gq; }
    else if (blockIdx.z == 1) { Ah = g_Kh; Al = g_Kl; Wh = g_Wkh; Wl = g_Wkl; bias = bk; C = gk; }
    else                      { Ah = g_Vh; Al = g_Vl; Wh = g_Wvh; Wl = g_Wvl; bias = bv; C = gv; }
    tc_gemm_body(Ah, Al, Wh, Wl, bias, C, 1, blockIdx.y * 128, blockIdx.x * 128);
}

// Output projection (row-major output).
__global__ __launch_bounds__(256) void out_mma_kernel(
    const float* __restrict__ bias, float* __restrict__ C)
{
    tc_gemm_body(g_Ch, g_Cl, g_Woh, g_Wol, bias, C, 0,
                 blockIdx.y * 128, blockIdx.x * 128);
}

// ---------------------------------------------------------------------------
// Flash attention (causal + key padding), fp32 (unchanged; passed at 7.6e-7).
// ---------------------------------------------------------------------------
__global__ __launch_bounds__(256) void attn_kernel(
    const float* __restrict__ Qh, const float* __restrict__ Kh,
    const float* __restrict__ Vh, const unsigned char* __restrict__ pad,
    float* __restrict__ ctx)
{
    __shared__ float Qs[64 * 64];
    __shared__ float KP[64 * 64];
    __shared__ float Vs[64 * 64];

    const int tid = threadIdx.x;
    const int tx = tid & 15;
    const int ty = tid >> 4;
    const int qt = blockIdx.x;
    const int h  = blockIdx.y;
    const int b  = blockIdx.z;

    const size_t headoff = ((size_t)(b * NH + h)) * S_LEN * DH;
    const float* Qb = Qh + headoff;
    const float* Kb = Kh + headoff;
    const float* Vb = Vh + headoff;

#pragma unroll
    for (int i = 0; i < 4; i++) {
        int idx = tid + i * 256;
        int row = idx >> 4;
        int c   = (idx & 15) << 2;
        float4 v = *(const float4*)(Qb + (size_t)(qt * 64 + row) * DH + c);
        Qs[row * 64 + c + 0] = v.x * 0.125f;
        Qs[row * 64 + c + 1] = v.y * 0.125f;
        Qs[row * 64 + c + 2] = v.z * 0.125f;
        Qs[row * 64 + c + 3] = v.w * 0.125f;
    }

    float m_i[4], l_i[4], o[4][4];
#pragma unroll
    for (int i = 0; i < 4; i++) {
        m_i[i] = -1e30f;
        l_i[i] = 0.0f;
#pragma unroll
        for (int j = 0; j < 4; j++) o[i][j] = 0.0f;
    }

    for (int kt = 0; kt <= qt; kt++) {
        __syncthreads();

#pragma unroll
        for (int i = 0; i < 4; i++) {
            int idx = tid + i * 256;
            int row = idx >> 4;
            int c   = (idx & 15) << 2;
            float4 kv = *(const float4*)(Kb + (size_t)(kt * 64 + row) * DH + c);
            KP[(c + 0) * 64 + ((row + c + 0) & 63)] = kv.x;
            KP[(c + 1) * 64 + ((row + c + 1) & 63)] = kv.y;
            KP[(c + 2) * 64 + ((row + c + 2) & 63)] = kv.z;
            KP[(c + 3) * 64 + ((row + c + 3) & 63)] = kv.w;
            float4 vv = *(const float4*)(Vb + (size_t)(kt * 64 + row) * DH + c);
            *(float4*)(Vs + row * 64 + c) = vv;
        }
        __syncthreads();

        float sc[4][4];
#pragma unroll
        for (int i = 0; i < 4; i++)
#pragma unroll
            for (int j = 0; j < 4; j++) sc[i][j] = 0.0f;

        for (int d = 0; d < 64; d++) {
            float br0 = KP[d * 64 + ((tx * 4 + 0 + d) & 63)];
            float br1 = KP[d * 64 + ((tx * 4 + 1 + d) & 63)];
            float br2 = KP[d * 64 + ((tx * 4 + 2 + d) & 63)];
            float br3 = KP[d * 64 + ((tx * 4 + 3 + d) & 63)];
#pragma unroll
            for (int i = 0; i < 4; i++) {
                float a = Qs[(ty * 4 + i) * 64 + d];
                sc[i][0] = fmaf(a, br0, sc[i][0]);
                sc[i][1] = fmaf(a, br1, sc[i][1]);
                sc[i][2] = fmaf(a, br2, sc[i][2]);
                sc[i][3] = fmaf(a, br3, sc[i][3]);
            }
        }

        const bool diag = (kt == qt);
#pragma unroll
        for (int j = 0; j < 4; j++) {
            int kj = kt * 64 + tx * 4 + j;
            bool pm = (pad[b * S_LEN + kj] != 0);
#pragma unroll
            for (int i = 0; i < 4; i++) {
                if (pm || (diag && (tx * 4 + j) > (ty * 4 + i)))
                    sc[i][j] = -1e9f;
            }
        }

#pragma unroll
        for (int i = 0; i < 4; i++) {
            float rm = fmaxf(fmaxf(sc[i][0], sc[i][1]), fmaxf(sc[i][2], sc[i][3]));
#pragma unroll
            for (int off = 8; off >= 1; off >>= 1)
                rm = fmaxf(rm, __shfl_xor_sync(0xffffffffu, rm, off));
            float mnew = fmaxf(m_i[i], rm);
            float corr = __expf(m_i[i] - mnew);
            m_i[i] = mnew;
            float rs = 0.0f;
#pragma unroll
            for (int j = 0; j < 4; j++) {
                sc[i][j] = __expf(sc[i][j] - mnew);
                rs += sc[i][j];
            }
#pragma unroll
            for (int off = 8; off >= 1; off >>= 1)
                rs += __shfl_xor_sync(0xffffffffu, rs, off);
            l_i[i] = l_i[i] * corr + rs;
#pragma unroll
            for (int j = 0; j < 4; j++) o[i][j] *= corr;
        }

        __syncthreads();
#pragma unroll
        for (int i = 0; i < 4; i++)
#pragma unroll
            for (int j = 0; j < 4; j++)
                KP[(ty * 4 + i) * 64 + tx * 4 + j] = sc[i][j];
        __syncthreads();

        for (int j = 0; j < 64; j++) {
            float4 vv = *(const float4*)(Vs + j * 64 + tx * 4);
#pragma unroll
            for (int i = 0; i < 4; i++) {
                float p = KP[(ty * 4 + i) * 64 + j];
                o[i][0] = fmaf(p, vv.x, o[i][0]);
                o[i][1] = fmaf(p, vv.y, o[i][1]);
                o[i][2] = fmaf(p, vv.z, o[i][2]);
                o[i][3] = fmaf(p, vv.w, o[i][3]);
            }
        }
    }

#pragma unroll
    for (int i = 0; i < 4; i++) {
        float inv = 1.0f / l_i[i];
        int s = qt * 64 + ty * 4 + i;
        float* dst = ctx + ((size_t)b * S_LEN + s) * DM + h * DH + tx * 4;
        dst[0] = o[i][0] * inv;
        dst[1] = o[i][1] * inv;
        dst[2] = o[i][2] * inv;
        dst[3] = o[i][3] * inv;
    }
}

// ---------------------------------------------------------------------------
// Launch. Inputs: Q, K, V, attn_mask, padding_mask, Wq, bq, Wk, bk, Wv, bv,
// Wo, bo. attn_mask is exactly causal (computed analytically).
// ---------------------------------------------------------------------------
extern "C" void kernel_launch(void* const* d_in, const int* in_sizes, int n_in,
                              void* d_out, int out_size)
{
    const float* Q  = (const float*)d_in[0];
    const float* K  = (const float*)d_in[1];
    const float* V  = (const float*)d_in[2];
    const unsigned char* pad = (const unsigned char*)d_in[4];
    const float* Wq = (const float*)d_in[5];
    const float* bq = (const float*)d_in[6];
    const float* Wk = (const float*)d_in[7];
    const float* bk = (const float*)d_in[8];
    const float* Wv = (const float*)d_in[9];
    const float* bv = (const float*)d_in[10];
    const float* Wo = (const float*)d_in[11];
    const float* bo = (const float*)d_in[12];
    float* out = (float*)d_out;

    float *gq, *gk, *gv, *gctx;
    cudaGetSymbolAddress((void**)&gq,   g_q);
    cudaGetSymbolAddress((void**)&gk,   g_k);
    cudaGetSymbolAddress((void**)&gv,   g_v);
    cudaGetSymbolAddress((void**)&gctx, g_ctx);
    __nv_bfloat16 *qh, *ql, *kh, *kl, *vh, *vl, *ch, *cl;
    __nv_bfloat16 *wqh, *wql, *wkh, *wkl, *wvh, *wvl, *woh, *wol;
    cudaGetSymbolAddress((void**)&qh, g_Qh);  cudaGetSymbolAddress((void**)&ql, g_Ql);
    cudaGetSymbolAddress((void**)&kh, g_Kh);  cudaGetSymbolAddress((void**)&kl, g_Kl);
    cudaGetSymbolAddress((void**)&vh, g_Vh);  cudaGetSymbolAddress((void**)&vl, g_Vl);
    cudaGetSymbolAddress((void**)&ch, g_Ch);  cudaGetSymbolAddress((void**)&cl, g_Cl);
    cudaGetSymbolAddress((void**)&wqh, g_Wqh); cudaGetSymbolAddress((void**)&wql, g_Wql);
    cudaGetSymbolAddress((void**)&wkh, g_Wkh); cudaGetSymbolAddress((void**)&wkl, g_Wkl);
    cudaGetSymbolAddress((void**)&wvh, g_Wvh); cudaGetSymbolAddress((void**)&wvl, g_Wvl);
    cudaGetSymbolAddress((void**)&woh, g_Woh); cudaGetSymbolAddress((void**)&wol, g_Wol);

    const int nAct4 = (M_ROWS * DM) / 4;   // 1,048,576
    const int nW4   = (DM * DM) / 4;       //   262,144
    split_bf16_kernel<<<(nAct4 + 255) / 256, 256>>>(Q,  qh,  ql,  nAct4);
    split_bf16_kernel<<<(nAct4 + 255) / 256, 256>>>(K,  kh,  kl,  nAct4);
    split_bf16_kernel<<<(nAct4 + 255) / 256, 256>>>(V,  vh,  vl,  nAct4);
    split_bf16_kernel<<<(nW4 + 255) / 256, 256>>>(Wq, wqh, wql, nW4);
    split_bf16_kernel<<<(nW4 + 255) / 256, 256>>>(Wk, wkh, wkl, nW4);
    split_bf16_kernel<<<(nW4 + 255) / 256, 256>>>(Wv, wvh, wvl, nW4);
    split_bf16_kernel<<<(nW4 + 255) / 256, 256>>>(Wo, woh, wol, nW4);

    dim3 gqkv(DM / 128, M_ROWS / 128, 3);   // (8, 32, 3)
    qkv_mma_kernel<<<gqkv, 256>>>(bq, bk, bv, gq, gk, gv);

    dim3 ga(S_LEN / 64, NH, B_SZ);          // (32, 16, 2)
    attn_kernel<<<ga, 256>>>(gq, gk, gv, pad, gctx);

    split_bf16_kernel<<<(nAct4 + 255) / 256, 256>>>(gctx, ch, cl, nAct4);

    dim3 gg(DM / 128, M_ROWS / 128);        // (8, 32)
    out_mma_kernel<<<gg, 256>>>(bo, out);
}